// round 14
// baseline (speedup 1.0000x reference)
#include <cuda_runtime.h>
#include <cstddef>

#define VOCABP 50001
#define EMB    200
#define HID    128
#define BATCH  256
#define TSTEPS 500
#define NC     6
#define DENSE  64
#define NGATE  512   // 4*HID
#define HOFF   203   // row offset of h-part inside W [331, 512]

#define SCAN_T    512                 // thread = (half = tid>>8, j = tid&255): cols {j, j+256}, k-half
#define SMEM_COLS 256                 // c1 columns (256..511) cached in SMEM, transposed
#define WPITCH    132                 // transposed weight pitch in floats (528B; bank stride 4)
#define GPITCH    512                 // gate staging pitch
// Ws(256*132) + h(4*128) + g(2*4*512) floats = 153,600 B (needs >48KB opt-in)
#define SCAN_SMEM_BYTES ((SMEM_COLS*WPITCH + 4*HID + 2*4*GPITCH) * 4)

#define TABR 32                       // vocab rows per tab tile

// ---------------- scratch (no allocations allowed) ----------------
__device__ float g_tab[2ull * VOCABP * NGATE];    // projected vocab tables, ~205 MB
__device__ float g_captab[2 * 4 * NGATE];         // cap one-hot projection + bias
__device__ float g_hfinal[2 * BATCH * HID];       // final hidden states per direction

// HW tanh (sm_75+): 1 MUFU op, ~2^-10 accuracy — recurrence-safe vs 1e-3 threshold
__device__ __forceinline__ float tanh_hw(float x) {
    float r; asm("tanh.approx.f32 %0, %1;" : "=f"(r) : "f"(x)); return r;
}
__device__ __forceinline__ float sig_hw(float x) {
    return fmaf(0.5f, tanh_hw(0.5f * x), 0.5f);
}

// packed fp32x2 FMA: d.lo += a.lo*b.lo ; d.hi += a.hi*b.hi   (exact fp32 per lane)
__device__ __forceinline__ void ffma2(unsigned long long& d,
                                      unsigned long long a, unsigned long long b) {
    asm("fma.rn.f32x2 %0, %1, %2, %0;" : "+l"(d) : "l"(a), "l"(b));
}
__device__ __forceinline__ float2 ull2f2(unsigned long long v) {
    float2 r; asm("mov.b64 {%0,%1}, %2;" : "=f"(r.x), "=f"(r.y) : "l"(v)); return r;
}
__device__ __forceinline__ unsigned long long fdup(float w) {
    unsigned long long r; asm("mov.b64 %0, {%1,%1};" : "=l"(r) : "f"(w)); return r;
}
__device__ __forceinline__ unsigned long long f2_to_ull(float x, float y) {
    unsigned long long r; asm("mov.b64 %0, {%1,%2};" : "=l"(r) : "f"(x), "f"(y)); return r;
}

// ---------------- kernel 1: Tab[d] = word_emb @ W_d[0:200,:]  (32-row tiles) ----------------
__global__ void __launch_bounds__(512) tab_kernel(const float* __restrict__ emb,
                                                  const float* __restrict__ Wfw,
                                                  const float* __restrict__ Wbw)
{
    __shared__ float es[EMB * TABR];   // [k][r] transposed tile, 25.6 KB
    const int d  = blockIdx.y;
    const int v0 = blockIdx.x * TABR;
    const float* __restrict__ W = d ? Wbw : Wfw;
    const int tid = threadIdx.x;

    for (int i = tid; i < TABR * EMB; i += 512) {
        int r = i / EMB, k = i % EMB;
        int v = v0 + r;
        es[k * TABR + r] = (v < VOCABP) ? emb[(size_t)v * EMB + k] : 0.0f;
    }
    __syncthreads();

    const int c = tid;   // gate column 0..511
    unsigned long long acc[TABR / 2];  // 16 packed pairs = 32 rows
#pragma unroll
    for (int p = 0; p < TABR / 2; p++) acc[p] = 0ull;

#pragma unroll 2
    for (int k = 0; k < EMB; k++) {
        unsigned long long wd = fdup(__ldg(&W[k * NGATE + c]));
        const ulonglong2* e2 = (const ulonglong2*)&es[k * TABR];
#pragma unroll
        for (int q = 0; q < TABR / 4; q++) {
            ulonglong2 e = e2[q];
            ffma2(acc[2 * q + 0], e.x, wd);
            ffma2(acc[2 * q + 1], e.y, wd);
        }
    }

    float* out = &g_tab[((size_t)d * VOCABP + v0) * NGATE + c];
#pragma unroll
    for (int p = 0; p < TABR / 2; p++) {
        float2 f = ull2f2(acc[p]);
        if (v0 + 2 * p     < VOCABP) out[(size_t)(2 * p)     * NGATE] = f.x;
        if (v0 + 2 * p + 1 < VOCABP) out[(size_t)(2 * p + 1) * NGATE] = f.y;
    }
}

// ---------------- kernel 2: cap table (+ bias folded in) ----------------
__global__ void captab_kernel(const float* __restrict__ cemb,
                              const float* __restrict__ Wfw, const float* __restrict__ bfw,
                              const float* __restrict__ Wbw, const float* __restrict__ bbw)
{
    int idx = blockIdx.x * blockDim.x + threadIdx.x;
    if (idx >= 2 * 4 * NGATE) return;
    int d  = idx / (4 * NGATE);
    int ci = (idx / NGATE) & 3;
    int c  = idx % NGATE;
    const float* W = d ? Wbw : Wfw;
    const float* b = d ? bbw : bfw;
    float v = b[c];
#pragma unroll
    for (int j = 0; j < 3; j++) v += cemb[ci * 3 + j] * W[(EMB + j) * NGATE + c];
    g_captab[idx] = v;
}

// ---------------- kernel 3: the recurrent scan ----------------
// grid = 128 CTAs: blockIdx.x>>6 = direction, (blockIdx.x&63)*4 = first batch row.
// Producer role: thread (half = tid>>8, j = tid&255) computes partial gates for
//   columns {j, j+256} x 4 rows over k in [half*64, half*64+64).
//   c0: all 64 k-weights in registers. c1: first 16 k in registers, rest from SMEM.
// Consumer role: thread (row = tid>>7, u = tid&127) loads its own x-gate values
//   and performs the gate update with HW tanh.
__global__ void __launch_bounds__(SCAN_T, 1) scan_kernel(const int* __restrict__ words,
                                                         const int* __restrict__ caps,
                                                         const float* __restrict__ Wfw,
                                                         const float* __restrict__ Wbw)
{
    extern __shared__ float sm[];
    float* Ws  = sm;                        // [SMEM_COLS][WPITCH] transposed c1 weights
    float* h_s = Ws + SMEM_COLS * WPITCH;   // [4][HID]
    float* g_s = h_s + 4 * HID;             // [2 halves][4][GPITCH]

    const int tid = threadIdx.x;
    const int d   = blockIdx.x >> 6;
    const int b0  = (blockIdx.x & 63) * 4;
    const float* __restrict__ W = d ? Wbw : Wfw;

    // stage c1 columns [256, 512) transposed: Ws[c-256][k]  (one-time cost)
    for (int i = tid; i < HID * SMEM_COLS; i += SCAN_T) {
        int k = i / SMEM_COLS, c = i % SMEM_COLS;   // coalesced global read
        Ws[c * WPITCH + k] = W[(HOFF + k) * NGATE + 256 + c];
    }
    h_s[tid] = 0.0f;   // 512 = 4*HID exactly

    const int half = tid >> 8;          // k-half: 0 -> [0,64), 1 -> [64,128)
    const int j    = tid & 255;
    const int c0   = j;                 // register-resident weights
    const int c1   = j + 256;
    const int k0   = half * 64;
    const float* __restrict__ tabd = &g_tab[(size_t)d * VOCABP * NGATE];
    const float* __restrict__ capd = &g_captab[d * 4 * NGATE];
    const float* __restrict__ wc1  = &Ws[j * WPITCH + k0];
    float* gh = g_s + half * 4 * GPITCH;   // this half's staging buffer

    // c0 weights: 64 fp32 -> 32 packed f32x2 registers (coalesced one-time load)
    unsigned long long wr[32];
#pragma unroll
    for (int kc = 0; kc < 16; kc++) {
        float w0 = __ldg(&W[(HOFF + k0 + 4 * kc + 0) * NGATE + c0]);
        float w1 = __ldg(&W[(HOFF + k0 + 4 * kc + 1) * NGATE + c0]);
        float w2 = __ldg(&W[(HOFF + k0 + 4 * kc + 2) * NGATE + c0]);
        float w3 = __ldg(&W[(HOFF + k0 + 4 * kc + 3) * NGATE + c0]);
        wr[2 * kc + 0] = f2_to_ull(w0, w1);
        wr[2 * kc + 1] = f2_to_ull(w2, w3);
    }
    // c1 head weights: k in [k0, k0+16) -> 8 packed registers (cuts smem weight wf by 25%)
    unsigned long long wz[8];
#pragma unroll
    for (int kc = 0; kc < 4; kc++) {
        float w0 = __ldg(&W[(HOFF + k0 + 4 * kc + 0) * NGATE + c1]);
        float w1 = __ldg(&W[(HOFF + k0 + 4 * kc + 1) * NGATE + c1]);
        float w2 = __ldg(&W[(HOFF + k0 + 4 * kc + 2) * NGATE + c1]);
        float w3 = __ldg(&W[(HOFF + k0 + 4 * kc + 3) * NGATE + c1]);
        wz[2 * kc + 0] = f2_to_ull(w0, w1);
        wz[2 * kc + 1] = f2_to_ull(w2, w3);
    }

    // consumer-role mapping: thread tid owns (row, unit)
    const int row = tid >> 7;      // 0..3
    const int u   = tid & 127;
    const int* __restrict__ wrow = &words[(b0 + row) * TSTEPS];
    const int* __restrict__ crow = &caps [(b0 + row) * TSTEPS];
    float cst = 0.0f, hh = 0.0f;

    __syncthreads();

    // prologue: indices for step 0
    int wv, cv;
    {
        int t0 = d ? (TSTEPS - 1) : 0;
        wv = __ldg(&wrow[t0]);
        cv = __ldg(&crow[t0]);
    }

    for (int t = 0; t < TSTEPS; t++) {
        // ---- step start: issue this step's x-gate loads (consumed in epilogue) ----
        const float* tr = &tabd[(size_t)wv * NGATE];
        const float* cr = &capd[(size_t)cv * NGATE];
        float xi = __ldg(&tr[u]);
        float xj = __ldg(&tr[u + 128]);
        float xf = __ldg(&tr[u + 256]);
        float xo = __ldg(&tr[u + 384]);
        float ki = __ldg(&cr[u]);
        float kj = __ldg(&cr[u + 128]);
        float kf = __ldg(&cr[u + 256]);
        float ko = __ldg(&cr[u + 384]);

        // prefetch next step's indices (L1-hot)
        {
            int tt = d ? (TSTEPS - 2 - t) : (t + 1);
            if (t + 1 >= TSTEPS) tt = 0;   // clamp: values unused
            wv = __ldg(&wrow[tt]);
            cv = __ldg(&crow[tt]);
        }

        // ---- producer: partial GEMM, 2 cols x 4 rows, k in [k0, k0+64) ----
        unsigned long long A0 = 0ull, A1 = 0ull, A2 = 0ull, A3 = 0ull;   // col c0 (reg w)
        unsigned long long E0 = 0ull, E1 = 0ull, E2 = 0ull, E3 = 0ull;   // col c1
        // k in [k0, k0+16): both columns' weights in registers (no weight LDS)
#pragma unroll
        for (int kc = 0; kc < 4; kc++) {
            const int kk = 4 * kc;
            ulonglong2 h0 = *(const ulonglong2*)&h_s[0 * HID + k0 + kk];  // broadcast
            ulonglong2 h1 = *(const ulonglong2*)&h_s[1 * HID + k0 + kk];
            ulonglong2 h2 = *(const ulonglong2*)&h_s[2 * HID + k0 + kk];
            ulonglong2 h3 = *(const ulonglong2*)&h_s[3 * HID + k0 + kk];
            unsigned long long w0x = wr[2 * kc + 0], w0y = wr[2 * kc + 1];
            unsigned long long w1x = wz[2 * kc + 0], w1y = wz[2 * kc + 1];
            ffma2(A0, h0.x, w0x); ffma2(A0, h0.y, w0y);
            ffma2(A1, h1.x, w0x); ffma2(A1, h1.y, w0y);
            ffma2(A2, h2.x, w0x); ffma2(A2, h2.y, w0y);
            ffma2(A3, h3.x, w0x); ffma2(A3, h3.y, w0y);
            ffma2(E0, h0.x, w1x); ffma2(E0, h0.y, w1y);
            ffma2(E1, h1.x, w1x); ffma2(E1, h1.y, w1y);
            ffma2(E2, h2.x, w1x); ffma2(E2, h2.y, w1y);
            ffma2(E3, h3.x, w1x); ffma2(E3, h3.y, w1y);
        }
        // k in [k0+16, k0+64): c1 weights from SMEM
#pragma unroll
        for (int kc = 4; kc < 16; kc++) {
            const int kk = 4 * kc;
            ulonglong2 w1 = *(const ulonglong2*)&wc1[kk];                 // LDS.128
            ulonglong2 h0 = *(const ulonglong2*)&h_s[0 * HID + k0 + kk];
            ulonglong2 h1 = *(const ulonglong2*)&h_s[1 * HID + k0 + kk];
            ulonglong2 h2 = *(const ulonglong2*)&h_s[2 * HID + k0 + kk];
            ulonglong2 h3 = *(const ulonglong2*)&h_s[3 * HID + k0 + kk];
            unsigned long long w0x = wr[2 * kc + 0], w0y = wr[2 * kc + 1];
            ffma2(A0, h0.x, w0x); ffma2(A0, h0.y, w0y);
            ffma2(A1, h1.x, w0x); ffma2(A1, h1.y, w0y);
            ffma2(A2, h2.x, w0x); ffma2(A2, h2.y, w0y);
            ffma2(A3, h3.x, w0x); ffma2(A3, h3.y, w0y);
            ffma2(E0, h0.x, w1.x); ffma2(E0, h0.y, w1.y);
            ffma2(E1, h1.x, w1.x); ffma2(E1, h1.y, w1.y);
            ffma2(E2, h2.x, w1.x); ffma2(E2, h2.y, w1.y);
            ffma2(E3, h3.x, w1.x); ffma2(E3, h3.y, w1.y);
        }
        {
            float2 f;
            f = ull2f2(A0); gh[0 * GPITCH + c0]       = f.x + f.y;
            f = ull2f2(A1); gh[1 * GPITCH + c0]       = f.x + f.y;
            f = ull2f2(A2); gh[2 * GPITCH + c0]       = f.x + f.y;
            f = ull2f2(A3); gh[3 * GPITCH + c0]       = f.x + f.y;
            f = ull2f2(E0); gh[0 * GPITCH + c0 + 256] = f.x + f.y;
            f = ull2f2(E1); gh[1 * GPITCH + c0 + 256] = f.x + f.y;
            f = ull2f2(E2); gh[2 * GPITCH + c0 + 256] = f.x + f.y;
            f = ull2f2(E3); gh[3 * GPITCH + c0 + 256] = f.x + f.y;
        }
        __syncthreads();

        // ---- consumer: gate update for (row, u); HW tanh/sigmoid ----
        {
            float gi = g_s[row * GPITCH + u]           + g_s[4 * GPITCH + row * GPITCH + u]           + xi + ki;
            float gj = g_s[row * GPITCH + u + HID]     + g_s[4 * GPITCH + row * GPITCH + u + HID]     + xj + kj;
            float gf = g_s[row * GPITCH + u + 2 * HID] + g_s[4 * GPITCH + row * GPITCH + u + 2 * HID] + xf + kf;
            float go = g_s[row * GPITCH + u + 3 * HID] + g_s[4 * GPITCH + row * GPITCH + u + 3 * HID] + xo + ko;
            cst = sig_hw(gf + 1.0f) * cst + sig_hw(gi) * tanh_hw(gj);
            hh  = sig_hw(go) * tanh_hw(cst);
            h_s[row * HID + u] = hh;
        }
        __syncthreads();
    }

    g_hfinal[((d * BATCH) + (b0 + row)) * HID + u] = hh;
}

// ---------------- kernel 4: dense head ----------------
__global__ void __launch_bounds__(256) dense_kernel(const float* __restrict__ W1,
                                                    const float* __restrict__ b1,
                                                    const float* __restrict__ W2,
                                                    const float* __restrict__ b2,
                                                    float* __restrict__ out)
{
    __shared__ float red[256];
    __shared__ float d1[DENSE];
    const int b = blockIdx.x, t = threadIdx.x;
    const int j = t & 63, q = t >> 6;
    const float* xin = (q < 2) ? &g_hfinal[b * HID + q * 64]
                               : &g_hfinal[(BATCH + b) * HID + (q - 2) * 64];
    const float* w   = &W1[(q * 64) * DENSE + j];
    float acc = 0.0f;
#pragma unroll 8
    for (int i = 0; i < 64; i++) acc += xin[i] * w[i * DENSE];
    red[t] = acc;
    __syncthreads();
    if (t < DENSE) {
        float a = red[t] + red[t + 64] + red[t + 128] + red[t + 192] + b1[t];
        d1[t] = (a > 0.0f) ? a : (__expf(a) - 1.0f);   // elu (exact path; outside recurrence)
    }
    __syncthreads();
    if (t < NC) {
        float a = b2[t];
#pragma unroll
        for (int k = 0; k < DENSE; k++) a += d1[k] * W2[k * NC + t];
        out[b * NC + t] = 1.0f / (1.0f + __expf(-a));  // sigmoid
    }
}

// ---------------- launch ----------------
extern "C" void kernel_launch(void* const* d_in, const int* in_sizes, int n_in,
                              void* d_out, int out_size)
{
    const int*   words = (const int*)  d_in[0];
    const int*   caps  = (const int*)  d_in[1];
    const float* emb   = (const float*)d_in[2];
    const float* cemb  = (const float*)d_in[3];
    const float* Wfw   = (const float*)d_in[4];
    const float* bfw   = (const float*)d_in[5];
    const float* Wbw   = (const float*)d_in[6];
    const float* bbw   = (const float*)d_in[7];
    const float* W1    = (const float*)d_in[8];
    const float* b1    = (const float*)d_in[9];
    const float* W2    = (const float*)d_in[10];
    const float* b2    = (const float*)d_in[11];
    float* out = (float*)d_out;

    cudaFuncSetAttribute(scan_kernel, cudaFuncAttributeMaxDynamicSharedMemorySize,
                         SCAN_SMEM_BYTES);

    captab_kernel<<<8, 512>>>(cemb, Wfw, bfw, Wbw, bbw);
    tab_kernel<<<dim3((VOCABP + TABR - 1) / TABR, 2), 512>>>(emb, Wfw, Wbw);
    scan_kernel<<<128, SCAN_T, SCAN_SMEM_BYTES>>>(words, caps, Wfw, Wbw);
    dense_kernel<<<BATCH, 256>>>(W1, b1, W2, b2, out);
}

// round 15
// speedup vs baseline: 1.1937x; 1.1937x over previous
#include <cuda_runtime.h>
#include <cstddef>

#define VOCABP 50001
#define EMB    200
#define HID    128
#define BATCH  256
#define TSTEPS 500
#define NC     6
#define DENSE  64
#define NGATE  512   // 4*HID
#define HOFF   203   // row offset of h-part inside W [331, 512]

#define SCAN_T    512                 // thread = (half = tid>>8, j = tid&255): cols {j, j+256}, k-half
#define SMEM_COLS 256                 // c1 columns (256..511) cached in SMEM, transposed
#define WPITCH    132                 // transposed weight pitch in floats (528B; bank stride 4)
#define GPITCH    512                 // gate staging pitch
// Ws(256*132) + h(4*128) + g(2*4*512) floats = 153,600 B (needs >48KB opt-in)
#define SCAN_SMEM_BYTES ((SMEM_COLS*WPITCH + 4*HID + 2*4*GPITCH) * 4)

// ---------------- scratch (no allocations allowed) ----------------
__device__ float g_tab[2ull * VOCABP * NGATE];    // projected vocab tables, ~205 MB
__device__ float g_captab[2 * 4 * NGATE];         // cap one-hot projection + bias
__device__ float g_hfinal[2 * BATCH * HID];       // final hidden states per direction

// HW tanh (sm_75+): 1 MUFU op, ~2^-11 accuracy — measured rel_err 1.45e-7 end-to-end
__device__ __forceinline__ float tanh_hw(float x) {
    float r; asm("tanh.approx.f32 %0, %1;" : "=f"(r) : "f"(x)); return r;
}
__device__ __forceinline__ float sig_hw(float x) {
    return fmaf(0.5f, tanh_hw(0.5f * x), 0.5f);
}

// packed fp32x2 FMA: d.lo += a.lo*b.lo ; d.hi += a.hi*b.hi   (exact fp32 per lane)
__device__ __forceinline__ void ffma2(unsigned long long& d,
                                      unsigned long long a, unsigned long long b) {
    asm("fma.rn.f32x2 %0, %1, %2, %0;" : "+l"(d) : "l"(a), "l"(b));
}
__device__ __forceinline__ float2 ull2f2(unsigned long long v) {
    float2 r; asm("mov.b64 {%0,%1}, %2;" : "=f"(r.x), "=f"(r.y) : "l"(v)); return r;
}
__device__ __forceinline__ unsigned long long fdup(float w) {
    unsigned long long r; asm("mov.b64 %0, {%1,%1};" : "=l"(r) : "f"(w)); return r;
}
__device__ __forceinline__ unsigned long long f2_to_ull(float x, float y) {
    unsigned long long r; asm("mov.b64 %0, {%1,%2};" : "=l"(r) : "f"(x), "f"(y)); return r;
}

// ---------------- kernel 1: Tab[d] = word_emb @ W_d[0:200,:] ----------------
__global__ void __launch_bounds__(512) tab_kernel(const float* __restrict__ emb,
                                                  const float* __restrict__ Wfw,
                                                  const float* __restrict__ Wbw)
{
    __shared__ float es[EMB * 16];   // [k][r] transposed tile, 12.8 KB
    const int d  = blockIdx.y;
    const int v0 = blockIdx.x * 16;
    const float* __restrict__ W = d ? Wbw : Wfw;
    const int tid = threadIdx.x;

    for (int i = tid; i < 16 * EMB; i += 512) {
        int r = i / EMB, k = i % EMB;
        int v = v0 + r;
        es[k * 16 + r] = (v < VOCABP) ? emb[(size_t)v * EMB + k] : 0.0f;
    }
    __syncthreads();

    const int c = tid;   // gate column 0..511
    unsigned long long acc[8];  // 8 packed pairs = 16 rows
#pragma unroll
    for (int p = 0; p < 8; p++) acc[p] = 0ull;

#pragma unroll 4
    for (int k = 0; k < EMB; k++) {
        unsigned long long wd = fdup(__ldg(&W[k * NGATE + c]));
        const ulonglong2* e2 = (const ulonglong2*)&es[k * 16];
        ulonglong2 ea = e2[0], eb = e2[1], ec = e2[2], ed = e2[3];
        ffma2(acc[0], ea.x, wd); ffma2(acc[1], ea.y, wd);
        ffma2(acc[2], eb.x, wd); ffma2(acc[3], eb.y, wd);
        ffma2(acc[4], ec.x, wd); ffma2(acc[5], ec.y, wd);
        ffma2(acc[6], ed.x, wd); ffma2(acc[7], ed.y, wd);
    }

    float* out = &g_tab[((size_t)d * VOCABP + v0) * NGATE + c];
#pragma unroll
    for (int p = 0; p < 8; p++) {
        float2 f = ull2f2(acc[p]);
        if (v0 + 2 * p     < VOCABP) out[(size_t)(2 * p)     * NGATE] = f.x;
        if (v0 + 2 * p + 1 < VOCABP) out[(size_t)(2 * p + 1) * NGATE] = f.y;
    }
}

// ---------------- kernel 2: cap table (+ bias folded in) ----------------
__global__ void captab_kernel(const float* __restrict__ cemb,
                              const float* __restrict__ Wfw, const float* __restrict__ bfw,
                              const float* __restrict__ Wbw, const float* __restrict__ bbw)
{
    int idx = blockIdx.x * blockDim.x + threadIdx.x;
    if (idx >= 2 * 4 * NGATE) return;
    int d  = idx / (4 * NGATE);
    int ci = (idx / NGATE) & 3;
    int c  = idx % NGATE;
    const float* W = d ? Wbw : Wfw;
    const float* b = d ? bbw : bfw;
    float v = b[c];
#pragma unroll
    for (int j = 0; j < 3; j++) v += cemb[ci * 3 + j] * W[(EMB + j) * NGATE + c];
    g_captab[idx] = v;
}

// ---------------- kernel 3: the recurrent scan ----------------
// grid = 128 CTAs: blockIdx.x>>6 = direction, (blockIdx.x&63)*4 = first batch row.
// Producer role: thread (half = tid>>8, j = tid&255) computes partial gates for
//   columns {j, j+256} x 4 rows over k in [half*64, half*64+64).
//   c0 weights in 32 packed f32x2 registers; c1 weights from SMEM.
// Consumer role: thread (row = tid>>7, u = tid&127) loads its own x-gate values
//   and performs the gate update with HW tanh/sigmoid.
__global__ void __launch_bounds__(SCAN_T, 1) scan_kernel(const int* __restrict__ words,
                                                         const int* __restrict__ caps,
                                                         const float* __restrict__ Wfw,
                                                         const float* __restrict__ Wbw)
{
    extern __shared__ float sm[];
    float* Ws  = sm;                        // [SMEM_COLS][WPITCH] transposed c1 weights
    float* h_s = Ws + SMEM_COLS * WPITCH;   // [4][HID]
    float* g_s = h_s + 4 * HID;             // [2 halves][4][GPITCH]

    const int tid = threadIdx.x;
    const int d   = blockIdx.x >> 6;
    const int b0  = (blockIdx.x & 63) * 4;
    const float* __restrict__ W = d ? Wbw : Wfw;

    // stage c1 columns [256, 512) transposed: Ws[c-256][k]  (one-time cost)
    for (int i = tid; i < HID * SMEM_COLS; i += SCAN_T) {
        int k = i / SMEM_COLS, c = i % SMEM_COLS;   // coalesced global read
        Ws[c * WPITCH + k] = W[(HOFF + k) * NGATE + 256 + c];
    }
    h_s[tid] = 0.0f;   // 512 = 4*HID exactly

    const int half = tid >> 8;          // k-half: 0 -> [0,64), 1 -> [64,128)
    const int j    = tid & 255;
    const int c0   = j;                 // register-resident weights
    const int k0   = half * 64;
    const float* __restrict__ tabd = &g_tab[(size_t)d * VOCABP * NGATE];
    const float* __restrict__ capd = &g_captab[d * 4 * NGATE];
    const float* __restrict__ wc1  = &Ws[j * WPITCH + k0];
    float* gh = g_s + half * 4 * GPITCH;   // this half's staging buffer

    // c0 weights: 64 fp32 -> 32 packed f32x2 registers (coalesced one-time load)
    unsigned long long wr[32];
#pragma unroll
    for (int kc = 0; kc < 16; kc++) {
        float w0 = __ldg(&W[(HOFF + k0 + 4 * kc + 0) * NGATE + c0]);
        float w1 = __ldg(&W[(HOFF + k0 + 4 * kc + 1) * NGATE + c0]);
        float w2 = __ldg(&W[(HOFF + k0 + 4 * kc + 2) * NGATE + c0]);
        float w3 = __ldg(&W[(HOFF + k0 + 4 * kc + 3) * NGATE + c0]);
        wr[2 * kc + 0] = f2_to_ull(w0, w1);
        wr[2 * kc + 1] = f2_to_ull(w2, w3);
    }

    // consumer-role mapping: thread tid owns (row, unit)
    const int row = tid >> 7;      // 0..3
    const int u   = tid & 127;
    const int* __restrict__ wrow = &words[(b0 + row) * TSTEPS];
    const int* __restrict__ crow = &caps [(b0 + row) * TSTEPS];
    float cst = 0.0f, hh = 0.0f;

    __syncthreads();

    // prologue: indices for step 0
    int wv, cv;
    {
        int t0 = d ? (TSTEPS - 1) : 0;
        wv = __ldg(&wrow[t0]);
        cv = __ldg(&crow[t0]);
    }

    for (int t = 0; t < TSTEPS; t++) {
        // ---- step start: issue this step's x-gate loads (consumed in epilogue) ----
        const float* tr = &tabd[(size_t)wv * NGATE];
        const float* cr = &capd[(size_t)cv * NGATE];
        float xi = __ldg(&tr[u]);
        float xj = __ldg(&tr[u + 128]);
        float xf = __ldg(&tr[u + 256]);
        float xo = __ldg(&tr[u + 384]);
        float ki = __ldg(&cr[u]);
        float kj = __ldg(&cr[u + 128]);
        float kf = __ldg(&cr[u + 256]);
        float ko = __ldg(&cr[u + 384]);

        // prefetch next step's indices (L1-hot)
        {
            int tt = d ? (TSTEPS - 2 - t) : (t + 1);
            if (t + 1 >= TSTEPS) tt = 0;   // clamp: values unused
            wv = __ldg(&wrow[tt]);
            cv = __ldg(&crow[tt]);
        }

        // ---- producer: partial GEMM, 2 cols x 4 rows, k in [k0, k0+64) ----
        unsigned long long A0 = 0ull, A1 = 0ull, A2 = 0ull, A3 = 0ull;   // col c0 (reg w)
        unsigned long long E0 = 0ull, E1 = 0ull, E2 = 0ull, E3 = 0ull;   // col c1 (smem w)
#pragma unroll
        for (int kc = 0; kc < 16; kc++) {
            const int kk = 4 * kc;
            ulonglong2 w1 = *(const ulonglong2*)&wc1[kk];                 // LDS.128
            ulonglong2 h0 = *(const ulonglong2*)&h_s[0 * HID + k0 + kk];  // broadcast
            ulonglong2 h1 = *(const ulonglong2*)&h_s[1 * HID + k0 + kk];
            ulonglong2 h2 = *(const ulonglong2*)&h_s[2 * HID + k0 + kk];
            ulonglong2 h3 = *(const ulonglong2*)&h_s[3 * HID + k0 + kk];
            unsigned long long w0x = wr[2 * kc + 0];
            unsigned long long w0y = wr[2 * kc + 1];
            ffma2(A0, h0.x, w0x); ffma2(A0, h0.y, w0y);
            ffma2(A1, h1.x, w0x); ffma2(A1, h1.y, w0y);
            ffma2(A2, h2.x, w0x); ffma2(A2, h2.y, w0y);
            ffma2(A3, h3.x, w0x); ffma2(A3, h3.y, w0y);
            ffma2(E0, h0.x, w1.x); ffma2(E0, h0.y, w1.y);
            ffma2(E1, h1.x, w1.x); ffma2(E1, h1.y, w1.y);
            ffma2(E2, h2.x, w1.x); ffma2(E2, h2.y, w1.y);
            ffma2(E3, h3.x, w1.x); ffma2(E3, h3.y, w1.y);
        }
        {
            float2 f;
            f = ull2f2(A0); gh[0 * GPITCH + c0]       = f.x + f.y;
            f = ull2f2(A1); gh[1 * GPITCH + c0]       = f.x + f.y;
            f = ull2f2(A2); gh[2 * GPITCH + c0]       = f.x + f.y;
            f = ull2f2(A3); gh[3 * GPITCH + c0]       = f.x + f.y;
            f = ull2f2(E0); gh[0 * GPITCH + c0 + 256] = f.x + f.y;
            f = ull2f2(E1); gh[1 * GPITCH + c0 + 256] = f.x + f.y;
            f = ull2f2(E2); gh[2 * GPITCH + c0 + 256] = f.x + f.y;
            f = ull2f2(E3); gh[3 * GPITCH + c0 + 256] = f.x + f.y;
        }
        __syncthreads();

        // ---- consumer: gate update for (row, u); HW tanh/sigmoid ----
        {
            float gi = g_s[row * GPITCH + u]           + g_s[4 * GPITCH + row * GPITCH + u]           + xi + ki;
            float gj = g_s[row * GPITCH + u + HID]     + g_s[4 * GPITCH + row * GPITCH + u + HID]     + xj + kj;
            float gf = g_s[row * GPITCH + u + 2 * HID] + g_s[4 * GPITCH + row * GPITCH + u + 2 * HID] + xf + kf;
            float go = g_s[row * GPITCH + u + 3 * HID] + g_s[4 * GPITCH + row * GPITCH + u + 3 * HID] + xo + ko;
            cst = sig_hw(gf + 1.0f) * cst + sig_hw(gi) * tanh_hw(gj);
            hh  = sig_hw(go) * tanh_hw(cst);
            h_s[row * HID + u] = hh;
        }
        __syncthreads();
    }

    g_hfinal[((d * BATCH) + (b0 + row)) * HID + u] = hh;
}

// ---------------- kernel 4: dense head ----------------
__global__ void __launch_bounds__(256) dense_kernel(const float* __restrict__ W1,
                                                    const float* __restrict__ b1,
                                                    const float* __restrict__ W2,
                                                    const float* __restrict__ b2,
                                                    float* __restrict__ out)
{
    __shared__ float red[256];
    __shared__ float d1[DENSE];
    const int b = blockIdx.x, t = threadIdx.x;
    const int j = t & 63, q = t >> 6;
    const float* xin = (q < 2) ? &g_hfinal[b * HID + q * 64]
                               : &g_hfinal[(BATCH + b) * HID + (q - 2) * 64];
    const float* w   = &W1[(q * 64) * DENSE + j];
    float acc = 0.0f;
#pragma unroll 8
    for (int i = 0; i < 64; i++) acc += xin[i] * w[i * DENSE];
    red[t] = acc;
    __syncthreads();
    if (t < DENSE) {
        float a = red[t] + red[t + 64] + red[t + 128] + red[t + 192] + b1[t];
        d1[t] = (a > 0.0f) ? a : (__expf(a) - 1.0f);   // elu (exact path; outside recurrence)
    }
    __syncthreads();
    if (t < NC) {
        float a = b2[t];
#pragma unroll
        for (int k = 0; k < DENSE; k++) a += d1[k] * W2[k * NC + t];
        out[b * NC + t] = 1.0f / (1.0f + __expf(-a));  // sigmoid
    }
}

// ---------------- launch ----------------
extern "C" void kernel_launch(void* const* d_in, const int* in_sizes, int n_in,
                              void* d_out, int out_size)
{
    const int*   words = (const int*)  d_in[0];
    const int*   caps  = (const int*)  d_in[1];
    const float* emb   = (const float*)d_in[2];
    const float* cemb  = (const float*)d_in[3];
    const float* Wfw   = (const float*)d_in[4];
    const float* bfw   = (const float*)d_in[5];
    const float* Wbw   = (const float*)d_in[6];
    const float* bbw   = (const float*)d_in[7];
    const float* W1    = (const float*)d_in[8];
    const float* b1    = (const float*)d_in[9];
    const float* W2    = (const float*)d_in[10];
    const float* b2    = (const float*)d_in[11];
    float* out = (float*)d_out;

    cudaFuncSetAttribute(scan_kernel, cudaFuncAttributeMaxDynamicSharedMemorySize,
                         SCAN_SMEM_BYTES);

    captab_kernel<<<8, 512>>>(cemb, Wfw, bfw, Wbw, bbw);
    tab_kernel<<<dim3((VOCABP + 15) / 16, 2), 512>>>(emb, Wfw, Wbw);
    scan_kernel<<<128, SCAN_T, SCAN_SMEM_BYTES>>>(words, caps, Wfw, Wbw);
    dense_kernel<<<BATCH, 256>>>(W1, b1, W2, b2, out);
}